// round 16
// baseline (speedup 1.0000x reference)
#include <cuda_runtime.h>

constexpr int Nn = 4096;   // z rows
constexpr int Mm = 1024;   // e rows
constexpr int Dd = 64;     // feature dim

constexpr int BK = 2048;                     // buckets per column
constexpr float LOb  = -6.0f;
constexpr float HIb  =  6.0f;
constexpr float INVW = BK / (HIb - LOb);

__device__ __forceinline__ int bucket_of(float v) {
    int k = (int)((v - LOb) * INVW);
    return min(max(k, 0), BK - 1);
}

// Scratch (no allocations allowed -> device globals)
__device__ float g_part[Dd];     // per-column partial sums
__device__ int   g_ctr;          // NN-block completion counter (0 at rest)

// ---------------------------------------------------------------------------
// Single fused kernel. Grid 96 x 1024:
//   blocks 0..63  : full-column NN for d = bx (gather z/e directly, bucket
//                   grouping, query, block-reduce -> g_part[d]; last block
//                   sums the 64 partials and plain-stores out[0]).
//   blocks 64..95 : mask + copy (2 float4 loads/thread, scalar stores).
__global__ void __launch_bounds__(1024) k_fused(const float* __restrict__ z,
                                                const float* __restrict__ e,
                                                const int* __restrict__ idx,
                                                float* __restrict__ out) {
    const int bx = blockIdx.x;
    const int t  = threadIdx.x;

    if (bx >= 64) {
        // ---------------- copy/mask block ----------------
        const int cb = bx - 64;              // 0..31
        #pragma unroll
        for (int i = 0; i < 2; i++) {
            int gid = cb * 2048 + i * 1024 + t;      // float4 index, 0..65535
            int row = gid >> 4;
            int col = (gid & 15) * 4;
            float4 v = reinterpret_cast<const float4*>(z)[gid];
            int k = idx[row];
            int base = gid * 4;
            // out+1 region is only 4B-aligned -> scalar stores
            out[1 + base + 0] = (col + 0 < k) ? v.x : 0.0f;
            out[1 + base + 1] = (col + 1 < k) ? v.y : 0.0f;
            out[1 + base + 2] = (col + 2 < k) ? v.z : 0.0f;
            out[1 + base + 3] = (col + 3 < k) ? v.w : 0.0f;
            out[1 + Nn * Dd + base + 0] = v.x;
            out[1 + Nn * Dd + base + 1] = v.y;
            out[1 + Nn * Dd + base + 2] = v.z;
            out[1 + Nn * Dd + base + 3] = v.w;
        }
        return;
    }

    // ---------------- NN block for column d = bx ----------------
    __shared__ float S[Nn];          // bucket-grouped column (16 KB)
    __shared__ int   cnt[BK];        // hist -> exclusive starts (8 KB)
    __shared__ int   wtot[32];
    __shared__ float red[32];
    __shared__ int   is_last;

    const int d = bx;
    const int lane = t & 31, wid = t >> 5;

    // Direct gathers (issue before first barrier; overlap the build).
    float x = e[t * Dd + d];
    float v[4];
    #pragma unroll
    for (int i = 0; i < 4; i++) v[i] = z[(i * 1024 + t) * Dd + d];

    cnt[t] = 0; cnt[t + 1024] = 0;
    __syncthreads();

    // ---- single atomic pass: histogram + within-bucket rank ----
    int b[4], r[4];
    #pragma unroll
    for (int i = 0; i < 4; i++) {
        b[i] = bucket_of(v[i]);
        r[i] = atomicAdd(&cnt[b[i]], 1);
    }
    __syncthreads();

    // ---- block exclusive scan (2 buckets per thread) ----
    int c0 = cnt[2 * t], c1 = cnt[2 * t + 1];
    int s = c0 + c1;
    int inc = s;
    #pragma unroll
    for (int o = 1; o < 32; o <<= 1) {
        int n = __shfl_up_sync(0xFFFFFFFFu, inc, o);
        if (lane >= o) inc += n;
    }
    if (lane == 31) wtot[wid] = inc;
    __syncthreads();
    if (wid == 0) {
        int ws = wtot[lane];
        int wi = ws;
        #pragma unroll
        for (int o = 1; o < 32; o <<= 1) {
            int n = __shfl_up_sync(0xFFFFFFFFu, wi, o);
            if (lane >= o) wi += n;
        }
        wtot[lane] = wi - ws;            // exclusive warp offsets
    }
    __syncthreads();
    int excl = (inc - s) + wtot[wid];
    cnt[2 * t]     = excl;
    cnt[2 * t + 1] = excl + c0;
    __syncthreads();

    // ---- scatter: plain stores (start + rank unique) ----
    #pragma unroll
    for (int i = 0; i < 4; i++)
        S[cnt[b[i]] + r[i]] = v[i];
    __syncthreads();

    // ---- query: own bucket + nearest nonempty bucket each side ----
    int k0 = bucket_of(x);
    int start = cnt[k0];
    int end   = (k0 < BK - 1) ? cnt[k0 + 1] : Nn;

    float best = 1e30f;
    for (int j = start; j < end; j++)
        best = fminf(best, fabsf(S[j] - x));

    if (start > 0) {                     // nearest nonempty bucket below
        int bb = bucket_of(S[start - 1]);
        int lo = cnt[bb];                // its segment is [lo, start)
        for (int j = lo; j < start; j++)
            best = fminf(best, fabsf(S[j] - x));
    }
    if (end < Nn) {                      // nearest nonempty bucket above
        int bb = bucket_of(S[end]);
        int hi = (bb < BK - 1) ? cnt[bb + 1] : Nn;
        for (int j = end; j < hi; j++)
            best = fminf(best, fabsf(S[j] - x));
    }

    // ---- block sum reduce -> g_part[d] ----
    float val = best * best;
    #pragma unroll
    for (int o = 16; o > 0; o >>= 1)
        val += __shfl_xor_sync(0xFFFFFFFFu, val, o);
    if (lane == 0) red[wid] = val;
    __syncthreads();
    if (wid == 0) {
        float sv = red[lane];
        #pragma unroll
        for (int o = 16; o > 0; o >>= 1)
            sv += __shfl_xor_sync(0xFFFFFFFFu, sv, o);
        if (lane == 0) {
            g_part[d] = sv;
            __threadfence();                 // publish before counting
            int old = atomicAdd(&g_ctr, 1);
            is_last = (old == 63);
        }
    }
    __syncthreads();

    // ---- last NN block: 64-float tail -> out[0] ----
    if (is_last && wid == 0) {
        float a = __ldcg(&g_part[lane]);
        float c = __ldcg(&g_part[lane + 32]);
        float sv = a + c;
        #pragma unroll
        for (int o = 16; o > 0; o >>= 1)
            sv += __shfl_xor_sync(0xFFFFFFFFu, sv, o);
        if (lane == 0) {
            out[0] = sv * (1.0f / (float)(Mm * Dd));
            g_ctr = 0;                       // reset for next graph replay
        }
    }
}

// ---------------------------------------------------------------------------
extern "C" void kernel_launch(void* const* d_in, const int* in_sizes, int n_in,
                              void* d_out, int out_size) {
    const float* z = (const float*)d_in[0];
    const float* e = (const float*)d_in[1];
    const int* idx = (const int*)d_in[2];
    float* out = (float*)d_out;

    k_fused<<<96, 1024>>>(z, e, idx, out);
}